// round 5
// baseline (speedup 1.0000x reference)
#include <cuda_runtime.h>
#include <cuda_bf16.h>
#include <math.h>
#include <stdint.h>

#define B_  2
#define S_  2048
#define H_  8
#define D_  64
#define DM_ 512
#define W_  128

typedef unsigned long long ull;

// ---------------- scratch (device globals; no allocation) ------------------
__device__ float g_q[B_*H_*S_*D_];
__device__ float g_k[B_*H_*S_*D_];
__device__ float g_v[B_*H_*S_*D_];
// split-bf16 operands (A side: X first, then attention output written by attn_k)
__device__ __nv_bfloat16 g_ah[B_*S_*DM_];
__device__ __nv_bfloat16 g_al[B_*S_*DM_];
__device__ __nv_bfloat16 g_wh[4*DM_*DM_];     // W^T hi: rows 0..1535 Wq,Wk,Wv; 1536.. Wo
__device__ __nv_bfloat16 g_wl[4*DM_*DM_];     // W^T lo

// ---------------- fp32x2 helpers -------------------------------------------
__device__ __forceinline__ ull pack2(float lo, float hi) {
    ull r; asm("mov.b64 %0, {%1, %2};" : "=l"(r) : "f"(lo), "f"(hi)); return r;
}
__device__ __forceinline__ void fma2(ull& d, ull a, ull b) {
    asm("fma.rn.f32x2 %0, %1, %2, %0;" : "+l"(d) : "l"(a), "l"(b));
}
__device__ __forceinline__ float2 unpk(ull v) {
    float2 f; asm("mov.b64 {%0, %1}, %2;" : "=f"(f.x), "=f"(f.y) : "l"(v)); return f;
}

__device__ __forceinline__ uint32_t smem_u32(const void* p) {
    uint32_t a;
    asm("{ .reg .u64 t; cvta.to.shared.u64 t, %1; cvt.u32.u64 %0, t; }" : "=r"(a) : "l"(p));
    return a;
}

// FMA-pipe exp (degree-5 exp2 poly). Handles -inf/-3e38 -> ~0.
__device__ __forceinline__ float fexp(float x) {
    float t = fmaxf(x * 1.4426950408889634f, -126.0f);
    float k = floorf(t);
    float f = t - k;
    float p = 1.33988744e-3f;
    p = fmaf(p, f, 9.61843735e-3f);
    p = fmaf(p, f, 5.55033251e-2f);
    p = fmaf(p, f, 2.40226479e-1f);
    p = fmaf(p, f, 6.93147203e-1f);
    p = fmaf(p, f, 1.0f);
    return __int_as_float(((int)k + 127) << 23) * p;
}

// ---------------- mma.sync building blocks (plain sm_103 PTX) --------------
#define LDSM4(r, addr) \
    asm volatile("ldmatrix.sync.aligned.m8n8.x4.shared.b16 {%0,%1,%2,%3}, [%4];" \
        : "=r"((r)[0]), "=r"((r)[1]), "=r"((r)[2]), "=r"((r)[3]) : "r"(addr))

#define MMA16816(c, a, b0, b1) \
    asm volatile("mma.sync.aligned.m16n8k16.row.col.f32.bf16.bf16.f32 " \
        "{%0,%1,%2,%3}, {%4,%5,%6,%7}, {%8,%9}, {%0,%1,%2,%3};" \
        : "+f"((c)[0]), "+f"((c)[1]), "+f"((c)[2]), "+f"((c)[3]) \
        : "r"((a)[0]), "r"((a)[1]), "r"((a)[2]), "r"((a)[3]), "r"(b0), "r"(b1))

__device__ __forceinline__ void cpa16(uint32_t s, const __nv_bfloat16* g) {
    asm volatile("cp.async.ca.shared.global [%0], [%1], 16;" :: "r"(s), "l"(g));
}

// ---------------------------------------------------------------------------
// Conversion kernels
// ---------------------------------------------------------------------------
__global__ void __launch_bounds__(256) conv_split_k(const float* __restrict__ X)
{
    int i = (blockIdx.x * 256 + threadIdx.x) * 4;
    float4 v = *(const float4*)(X + i);
    __nv_bfloat16 h0 = __float2bfloat16(v.x);
    __nv_bfloat16 h1 = __float2bfloat16(v.y);
    __nv_bfloat16 h2 = __float2bfloat16(v.z);
    __nv_bfloat16 h3 = __float2bfloat16(v.w);
    __nv_bfloat16 l0 = __float2bfloat16(v.x - __bfloat162float(h0));
    __nv_bfloat16 l1 = __float2bfloat16(v.y - __bfloat162float(h1));
    __nv_bfloat16 l2 = __float2bfloat16(v.z - __bfloat162float(h2));
    __nv_bfloat16 l3 = __float2bfloat16(v.w - __bfloat162float(h3));
    *(__nv_bfloat162*)(g_ah + i)     = __nv_bfloat162(h0, h1);
    *(__nv_bfloat162*)(g_ah + i + 2) = __nv_bfloat162(h2, h3);
    *(__nv_bfloat162*)(g_al + i)     = __nv_bfloat162(l0, l1);
    *(__nv_bfloat162*)(g_al + i + 2) = __nv_bfloat162(l2, l3);
}

__global__ void __launch_bounds__(256) conv_w_k(const float* __restrict__ Wq,
                                                const float* __restrict__ Wk,
                                                const float* __restrict__ Wv,
                                                const float* __restrict__ Wo)
{
    const float* Wsrc = (blockIdx.z == 0) ? Wq : (blockIdx.z == 1 ? Wk :
                        (blockIdx.z == 2 ? Wv : Wo));
    __shared__ float t[32][33];
    int bn = blockIdx.x * 32;
    int bk = blockIdx.y * 32;
    int lx = threadIdx.x & 31, ly = threadIdx.x >> 5;
#pragma unroll
    for (int i = 0; i < 32; i += 8)
        t[ly + i][lx] = Wsrc[(bk + ly + i) * DM_ + bn + lx];
    __syncthreads();
    int rowbase = blockIdx.z * DM_;
#pragma unroll
    for (int i = 0; i < 32; i += 8) {
        int r = ly + i;
        float x = t[lx][r];
        __nv_bfloat16 h = __float2bfloat16(x);
        __nv_bfloat16 l = __float2bfloat16(x - __bfloat162float(h));
        long idx = (long)(rowbase + bn + r) * DM_ + bk + lx;
        g_wh[idx] = h;
        g_wl[idx] = l;
    }
}

// ---------------------------------------------------------------------------
// mma.sync split-bf16 GEMM (unchanged from passing round 4).
// ---------------------------------------------------------------------------
#define GSM_BYTES (2 * 40960)

__device__ __forceinline__ void stage(uint32_t sb, int st, int m0, int nbase, int k0)
{
    const int tid = threadIdx.x;
#pragma unroll
    for (int i = 0; i < 2; i++) {
        int u = tid + (i << 8);
        int r = u >> 2, seg = u & 3;
        uint32_t so = sb + st * 40960 + r * 80 + seg * 16;
        long ga = (long)(m0 + r) * DM_ + k0 + seg * 8;
        long gb = (long)(nbase + r) * DM_ + k0 + seg * 8;
        cpa16(so,         g_ah + ga);
        cpa16(so + 10240, g_al + ga);
        cpa16(so + 20480, g_wh + gb);
        cpa16(so + 30720, g_wl + gb);
    }
    asm volatile("cp.async.commit_group;" ::: "memory");
}

__device__ __forceinline__ void compute_chunk(uint32_t sb, int st, float acc[2][8][4])
{
    const int lane = threadIdx.x & 31, w = threadIdx.x >> 5;
    const int wM = (w & 3) * 32, wN = (w >> 2) * 64;
    uint32_t base = sb + st * 40960;
    const int arow = wM + (lane & 15);
    const int achk = (lane >> 4) * 16;
    const int brow = wN + ((lane >> 4) ? 8 : 0) + (lane & 7);
    const int bchk = ((lane >> 3) & 1) * 16;

#pragma unroll
    for (int kk = 0; kk < 2; kk++) {
        const uint32_t kb = kk * 32;
        uint32_t a_hi[2][4], a_lo[2][4];
#pragma unroll
        for (int mt = 0; mt < 2; mt++) {
            uint32_t ad = base + (arow + mt * 16) * 80 + kb + achk;
            LDSM4(a_hi[mt], ad);
            LDSM4(a_lo[mt], ad + 10240);
        }
#pragma unroll
        for (int nb = 0; nb < 4; nb++) {
            uint32_t bd = base + 20480 + (brow + nb * 16) * 80 + kb + bchk;
            uint32_t bh[4], bl[4];
            LDSM4(bh, bd);
            LDSM4(bl, bd + 10240);
#pragma unroll
            for (int mt = 0; mt < 2; mt++) {
                MMA16816(acc[mt][nb * 2 + 0], a_hi[mt], bh[0], bh[1]);
                MMA16816(acc[mt][nb * 2 + 0], a_hi[mt], bl[0], bl[1]);
                MMA16816(acc[mt][nb * 2 + 0], a_lo[mt], bh[0], bh[1]);
                MMA16816(acc[mt][nb * 2 + 1], a_hi[mt], bh[2], bh[3]);
                MMA16816(acc[mt][nb * 2 + 1], a_hi[mt], bl[2], bl[3]);
                MMA16816(acc[mt][nb * 2 + 1], a_lo[mt], bh[2], bh[3]);
            }
        }
    }
}

__device__ __forceinline__ void gemm_mainloop(uint32_t sb, int m0, int nbase,
                                              float acc[2][8][4])
{
#pragma unroll
    for (int mt = 0; mt < 2; mt++)
#pragma unroll
        for (int nf = 0; nf < 8; nf++)
#pragma unroll
            for (int e = 0; e < 4; e++) acc[mt][nf][e] = 0.f;

    stage(sb, 0, m0, nbase, 0);
    for (int c = 0; c < 16; c++) {
        if (c < 15) {
            stage(sb, (c + 1) & 1, m0, nbase, (c + 1) * 32);
            asm volatile("cp.async.wait_group 1;" ::: "memory");
        } else {
            asm volatile("cp.async.wait_group 0;" ::: "memory");
        }
        __syncthreads();
        compute_chunk(sb, c & 1, acc);
        __syncthreads();
    }
}

// QKV projection: head-major scatter.
__global__ void __launch_bounds__(256, 2) mma_gemm_qkv()
{
    extern __shared__ char sm[];
    uint32_t sb = smem_u32(sm);
    const int m0 = blockIdx.y << 7;
    const int nbase = blockIdx.x << 7;
    float acc[2][8][4];
    gemm_mainloop(sb, m0, nbase, acc);

    const int lane = threadIdx.x & 31, w = threadIdx.x >> 5;
    const int wM = (w & 3) * 32, wN = (w >> 2) * 64;
#pragma unroll
    for (int mt = 0; mt < 2; mt++) {
        int r0 = m0 + wM + mt * 16 + (lane >> 2);
        int b = r0 >> 11, s = r0 & (S_ - 1);
#pragma unroll
        for (int nb = 0; nb < 4; nb++) {
#pragma unroll
            for (int nf = 0; nf < 2; nf++) {
                float* c = acc[mt][nb * 2 + nf];
                int n = nbase + wN + nb * 16 + nf * 8 + (lane & 3) * 2;
                int mat = n >> 9, cc = n & 511;
                int h = cc >> 6, d = cc & 63;
                float* outp = (mat == 0) ? g_q : (mat == 1 ? g_k : g_v);
                long o0 = (((long)b * H_ + h) * S_ + s) * D_ + d;
                *(float2*)(outp + o0)          = make_float2(c[0], c[1]);
                *(float2*)(outp + o0 + 8 * D_) = make_float2(c[2], c[3]);
            }
        }
    }
}

// Output projection: row-major store to C.
__global__ void __launch_bounds__(256, 2) mma_gemm_out(float* __restrict__ C)
{
    extern __shared__ char sm[];
    uint32_t sb = smem_u32(sm);
    const int m0 = blockIdx.y << 7;
    const int nbase = blockIdx.x << 7;
    float acc[2][8][4];
    gemm_mainloop(sb, m0, 3 * DM_ + nbase, acc);

    const int lane = threadIdx.x & 31, w = threadIdx.x >> 5;
    const int wM = (w & 3) * 32, wN = (w >> 2) * 64;
#pragma unroll
    for (int mt = 0; mt < 2; mt++) {
        int r0 = m0 + wM + mt * 16 + (lane >> 2);
#pragma unroll
        for (int nb = 0; nb < 4; nb++) {
#pragma unroll
            for (int nf = 0; nf < 2; nf++) {
                float* c = acc[mt][nb * 2 + nf];
                int n = nbase + wN + nb * 16 + nf * 8 + (lane & 3) * 2;
                *(float2*)(C + (long)r0 * DM_ + n)       = make_float2(c[0], c[1]);
                *(float2*)(C + (long)(r0 + 8) * DM_ + n) = make_float2(c[2], c[3]);
            }
        }
    }
}

// ---------------------------------------------------------------------------
// Sliding-window attention, f32x2 packed matmuls + FMA-pipe exp.
// Epilogue writes split-bf16 directly into g_ah/g_al (consumed by out-proj).
// ---------------------------------------------------------------------------
#define ATT_SMEM_FLOATS (64*66 + 192*64 + 192*64)
#define ATT_SMEM_BYTES  (ATT_SMEM_FLOATS * 4)

__global__ void __launch_bounds__(256, 1) attn_k()
{
    extern __shared__ float smf[];
    float* Qs = smf;                 // [64][66]
    float* Ks = smf + 64 * 66;       // [192][64]
    float* Vs = Ks + 192 * 64;       // [192][64]
    float* Ss = smf;                 // [64][193] alias over Qs+Ks

    const int tid = threadIdx.x;
    const int s0 = blockIdx.x << 6;
    const int h  = blockIdx.y;
    const int b  = blockIdx.z;
    const int base = ((b * H_ + h) * S_) * D_;

#pragma unroll
    for (int it = 0; it < 4; it++) {
        int idx = tid + it * 256;
        int qq = idx >> 4;
        int dc = (idx & 15) << 2;
        float4 qv = *(const float4*)(g_q + base + (s0 + qq) * D_ + dc);
        Qs[qq * 66 + dc + 0] = qv.x;
        Qs[qq * 66 + dc + 1] = qv.y;
        Qs[qq * 66 + dc + 2] = qv.z;
        Qs[qq * 66 + dc + 3] = qv.w;
    }
#pragma unroll
    for (int it = 0; it < 12; it++) {
        int idx = tid + it * 256;
        int jr = idx >> 4;
        int dc = (idx & 15) << 2;
        int kg = s0 - (W_ - 1) + jr;
        float4 kv = make_float4(0.f, 0.f, 0.f, 0.f);
        float4 vv = make_float4(0.f, 0.f, 0.f, 0.f);
        if (kg >= 0) {
            kv = *(const float4*)(g_k + base + kg * D_ + dc);
            vv = *(const float4*)(g_v + base + kg * D_ + dc);
        }
        *(float4*)(Ks + jr * 64 + dc) = kv;
        *(float4*)(Vs + jr * 64 + dc) = vv;
    }
    __syncthreads();

    // phase 1: S = Q K^T (f32x2)
    const int qg = tid & 15;
    const int jg = tid >> 4;
    const int jb = jg * 12;
    ull acc2[4][12];
#pragma unroll
    for (int r = 0; r < 4; r++)
#pragma unroll
        for (int u = 0; u < 12; u++) acc2[r][u] = 0ull;

#pragma unroll 4
    for (int d = 0; d < 64; d += 2) {
        ull qv[4];
#pragma unroll
        for (int r = 0; r < 4; r++)
            qv[r] = *(ull*)(&Qs[(qg + 16 * r) * 66 + d]);
#pragma unroll
        for (int u = 0; u < 12; u++) {
            ull kv = *(ull*)(&Ks[(jb + u) * 64 + d]);
            fma2(acc2[0][u], qv[0], kv);
            fma2(acc2[1][u], qv[1], kv);
            fma2(acc2[2][u], qv[2], kv);
            fma2(acc2[3][u], qv[3], kv);
        }
    }
    __syncthreads();

#pragma unroll
    for (int r = 0; r < 4; r++) {
        int i  = qg + 16 * r;
        int lo = (i > (W_ - 1) - s0) ? i : ((W_ - 1) - s0);
        int hi = i + (W_ - 1);
#pragma unroll
        for (int u = 0; u < 12; u++) {
            int j = jb + u;
            float2 f = unpk(acc2[r][u]);
            float sv = (f.x + f.y) * 0.125f;
            Ss[i * 193 + j] = (j >= lo && j <= hi) ? sv : -3.0e38f;
        }
    }
    __syncthreads();

    // phase 2: row softmax, exp on FMA pipe
    {
        const int w = tid >> 5, lane = tid & 31;
#pragma unroll
        for (int rr = 0; rr < 8; rr++) {
            float* row = Ss + ((w << 3) + rr) * 193;
            float m = -3.0e38f;
#pragma unroll
            for (int c = lane; c < 192; c += 32) m = fmaxf(m, row[c]);
#pragma unroll
            for (int msk = 16; msk >= 1; msk >>= 1)
                m = fmaxf(m, __shfl_xor_sync(0xffffffffu, m, msk));
            float ssum = 0.f;
#pragma unroll
            for (int c = lane; c < 192; c += 32) {
                float e = fexp(row[c] - m);
                row[c] = e;
                ssum += e;
            }
#pragma unroll
            for (int msk = 16; msk >= 1; msk >>= 1)
                ssum += __shfl_xor_sync(0xffffffffu, ssum, msk);
            float inv = 1.0f / ssum;
#pragma unroll
            for (int c = lane; c < 192; c += 32) row[c] *= inv;
        }
    }
    __syncthreads();

    // phase 3: O = P V (f32x2); epilogue writes split-bf16 into g_ah/g_al
    {
        const int qg3 = tid & 15;
        const int dg  = tid >> 4;
        ull o2[4][2];
#pragma unroll
        for (int r = 0; r < 4; r++) { o2[r][0] = 0ull; o2[r][1] = 0ull; }

#pragma unroll 4
        for (int j = 0; j < 192; j++) {
            float4 vv = *(float4*)(Vs + j * 64 + dg * 4);
            ull v0 = pack2(vv.x, vv.y);
            ull v1 = pack2(vv.z, vv.w);
#pragma unroll
            for (int r = 0; r < 4; r++) {
                float p = Ss[(qg3 + 16 * r) * 193 + j];
                ull pp = pack2(p, p);
                fma2(o2[r][0], pp, v0);
                fma2(o2[r][1], pp, v1);
            }
        }
#pragma unroll
        for (int r = 0; r < 4; r++) {
            int q = qg3 + 16 * r;
            float2 p0 = unpk(o2[r][0]);
            float2 p1 = unpk(o2[r][1]);
            float o[4] = {p0.x, p0.y, p1.x, p1.y};
            long idx = ((long)(b * S_ + s0 + q)) * DM_ + h * D_ + dg * 4;
            __nv_bfloat16 hh[4], ll[4];
#pragma unroll
            for (int e = 0; e < 4; e++) {
                hh[e] = __float2bfloat16(o[e]);
                ll[e] = __float2bfloat16(o[e] - __bfloat162float(hh[e]));
            }
            *(__nv_bfloat162*)(g_ah + idx)     = __nv_bfloat162(hh[0], hh[1]);
            *(__nv_bfloat162*)(g_ah + idx + 2) = __nv_bfloat162(hh[2], hh[3]);
            *(__nv_bfloat162*)(g_al + idx)     = __nv_bfloat162(ll[0], ll[1]);
            *(__nv_bfloat162*)(g_al + idx + 2) = __nv_bfloat162(ll[2], ll[3]);
        }
    }
}

// ---------------------------------------------------------------------------
extern "C" void kernel_launch(void* const* d_in, const int* in_sizes, int n_in,
                              void* d_out, int out_size)
{
    const float* x  = (const float*)d_in[0];
    const float* Wq = (const float*)d_in[1];
    const float* Wk = (const float*)d_in[2];
    const float* Wv = (const float*)d_in[3];
    const float* Wo = (const float*)d_in[4];
    float* out = (float*)d_out;

    cudaFuncSetAttribute(mma_gemm_qkv, cudaFuncAttributeMaxDynamicSharedMemorySize, GSM_BYTES);
    cudaFuncSetAttribute(mma_gemm_out, cudaFuncAttributeMaxDynamicSharedMemorySize, GSM_BYTES);
    cudaFuncSetAttribute(attn_k, cudaFuncAttributeMaxDynamicSharedMemorySize, ATT_SMEM_BYTES);

    conv_split_k<<<(B_*S_*DM_) / 1024, 256>>>(x);
    conv_w_k<<<dim3(16, 16, 4), 256>>>(Wq, Wk, Wv, Wo);
    mma_gemm_qkv<<<dim3(12, 32), 256, GSM_BYTES>>>();
    attn_k<<<dim3(S_ / 64, H_, B_), 256, ATT_SMEM_BYTES>>>();
    mma_gemm_out<<<dim3(4, 32), 256, GSM_BYTES>>>(out);
}